// round 14
// baseline (speedup 1.0000x reference)
#include <cuda_runtime.h>
#include <cuda_fp16.h>
#include <math.h>
#include <stdint.h>

#define B_  512
#define F_  1280
#define H_  2560
#define KK  8
#define E_  9

#define CH   64
#define NCH  (F_/CH)                // 20
#define SAE  72
#define ROWB (SAE*2)                // 144
#define ABUF_BYTES (128*ROWB)
#define BBUF_BYTES (128*ROWB)
#define STAGE_BYTES (ABUF_BYTES+BBUF_BYTES)  // 36864
#define A_OFF 0
#define B_OFF ABUF_BYTES
#define NSTG 3
#define DYN_BYTES (NSTG*STAGE_BYTES)  // 110592 -> 2 CTAs/SM
#define HTS 130
#define EP_W2_OFF  66560
#define EP_B1_OFF  70656

#define NXC   160                   // conv_x CTAs
#define NGRP  180                   // (e,nb) flag groups

__device__ __half gW[(size_t)E_*H_*F_];       // W1^T fp16 [e][n][k]
__device__ __half gX[(size_t)B_*F_];          // x fp16 [b][k]
__device__ float gPart[(size_t)E_*20*B_*KK];  // [e][nb][b][8]
__device__ int gXDone;
__device__ int gDone[NGRP];

__device__ __forceinline__ uint32_t smem_u32(const void* p){
    uint32_t a; asm("{ .reg .u64 t; cvta.to.shared.u64 t, %1; cvt.u32.u64 %0, t; }":"=r"(a):"l"(p)); return a;
}
#define CP16(dst,src) asm volatile("cp.async.cg.shared.global [%0], [%1], 16;"::"r"(dst),"l"(src):"memory")
#define LDM4(r,addr) asm volatile("ldmatrix.sync.aligned.m8n8.x4.shared.b16 {%0,%1,%2,%3}, [%4];" \
    : "=r"((r)[0]),"=r"((r)[1]),"=r"((r)[2]),"=r"((r)[3]) : "r"(addr))
__device__ __forceinline__ void mma_f16(float* c, const uint32_t* a, const uint32_t* b){
    asm volatile("mma.sync.aligned.m16n8k16.row.col.f32.f16.f16.f32 "
        "{%0,%1,%2,%3},{%4,%5,%6,%7},{%8,%9},{%0,%1,%2,%3};"
        : "+f"(c[0]),"+f"(c[1]),"+f"(c[2]),"+f"(c[3])
        : "r"(a[0]),"r"(a[1]),"r"(a[2]),"r"(a[3]),"r"(b[0]),"r"(b[1]));
}
__device__ __forceinline__ uint32_t pack2(float a, float b){
    __half2 h = __floats2half2_rn(a, b);
    return *reinterpret_cast<uint32_t*>(&h);
}

__global__ void reset_kernel(){
    int i = threadIdx.x;
    if(i == 0) gXDone = 0;
    if(i < NGRP) gDone[i] = 0;
}

// bid layout (after NXC conv_x bids):
//   [0,800):   conv e0, e1
//   then 7 blocks of 480: [gemm(e=blk) 80 | conv(e=blk+2) 400]
//   then 160:  gemm e7, e8
__global__ __launch_bounds__(256,2) void fused_kernel(const float* __restrict__ W1,
                                                      const float* __restrict__ W2,
                                                      const float* __restrict__ b1,
                                                      const float* __restrict__ x){
    extern __shared__ char dyn[];
    const int tid = threadIdx.x, lane = tid & 31, wid = tid >> 5;
    int bid = blockIdx.x;

    // ---- conv_x: 163840 float4s / 160 CTAs = 4/thread
    if(bid < NXC){
        int base = bid*1024 + tid;
#pragma unroll
        for(int u=0; u<4; u++){
            int i = base + u*256;
            float4 v = ((const float4*)x)[i];
            uint2 o;
            o.x = pack2(v.x, v.y);
            o.y = pack2(v.z, v.w);
            ((uint2*)gX)[i] = o;
        }
        __threadfence();
        __syncthreads();
        if(tid == 0) atomicAdd(&gXDone, 1);
        return;
    }
    bid -= NXC;

    int isConv, e, t;
    if(bid < 800){ isConv = 1; e = bid/400; t = bid%400; }
    else{
        int r = bid - 800;
        int blk = r/480, off = r%480;
        if(blk < 7){
            if(off < 80){ isConv = 0; e = blk;   t = off; }
            else        { isConv = 1; e = blk+2; t = off-80; }
        } else {
            int r2 = r - 3360;
            isConv = 0; e = 7 + r2/80; t = r2%80;
        }
    }

    if(isConv){
        // ---- conv tile: 64k x 128n at (e, kc, nb)
        float (*s)[129] = (float(*)[129])dyn;
        int nb = t % 20, kc = t / 20;
        const float* src = W1 + ((size_t)e*F_ + (size_t)kc*64)*H_ + (size_t)nb*128;
        for(int i=tid; i<64*128; i+=256){
            int kk = i>>7, r = i&127;
            s[kk][r] = src[(size_t)kk*H_ + r];
        }
        __syncthreads();
        int kg = tid & 7, rbase = tid >> 3;
#pragma unroll
        for(int u=0; u<4; u++){
            int row = u*32 + rbase;
            uint4 o;
            o.x = pack2(s[kg*8+0][row], s[kg*8+1][row]);
            o.y = pack2(s[kg*8+2][row], s[kg*8+3][row]);
            o.z = pack2(s[kg*8+4][row], s[kg*8+5][row]);
            o.w = pack2(s[kg*8+6][row], s[kg*8+7][row]);
            size_t off = (size_t)e*H_*F_ + (size_t)(nb*128+row)*F_ + kc*64 + kg*8;
            *(uint4*)(gW+off) = o;
        }
        __threadfence();
        __syncthreads();
        if(tid == 0) atomicAdd(&gDone[e*20+nb], 1);
        return;
    }

    // ---- gemm tile: t -> nb = t>>2, mb = t&3   (R9 body, m0/n0 from decode)
    const int mb = t & 3, nb = t >> 2;
    const int m0 = mb*128, n0 = nb*128;
    if(tid == 0){
        while(atomicAdd(&gDone[e*20+nb], 0) < 20) __nanosleep(64);
        while(atomicAdd(&gXDone, 0) < NXC) __nanosleep(64);
    }
    __syncthreads();
    __threadfence();

    const int warp_m = wid & 3, warp_n = wid >> 2;
    const uint32_t dynU = smem_u32(dyn);
    const int seg = tid & 7;
    const __half* gA = gX + (size_t)m0*F_;
    const __half* gB = gW + ((size_t)e*H_ + n0)*F_;
    const int r0 = tid>>3, r1 = (tid+256)>>3, r2 = (tid+512)>>3, r3 = (tid+768)>>3;

    uint32_t stB[NSTG];
#pragma unroll
    for(int s=0;s<NSTG;s++) stB[s] = dynU + s*STAGE_BYTES;

#define ISSUE(c) do{ \
    uint32_t st_ = stB[(c)%NSTG]; int ko_ = (c)*CH + seg*8; \
    CP16(st_+A_OFF + r0*ROWB + seg*16, gA + (size_t)r0*F_ + ko_); \
    CP16(st_+A_OFF + r1*ROWB + seg*16, gA + (size_t)r1*F_ + ko_); \
    CP16(st_+A_OFF + r2*ROWB + seg*16, gA + (size_t)r2*F_ + ko_); \
    CP16(st_+A_OFF + r3*ROWB + seg*16, gA + (size_t)r3*F_ + ko_); \
    CP16(st_+B_OFF + r0*ROWB + seg*16, gB + (size_t)r0*F_ + ko_); \
    CP16(st_+B_OFF + r1*ROWB + seg*16, gB + (size_t)r1*F_ + ko_); \
    CP16(st_+B_OFF + r2*ROWB + seg*16, gB + (size_t)r2*F_ + ko_); \
    CP16(st_+B_OFF + r3*ROWB + seg*16, gB + (size_t)r3*F_ + ko_); \
    asm volatile("cp.async.commit_group;":::"memory"); }while(0)

    const uint32_t aBase = A_OFF + (uint32_t)(warp_m*32 + (lane & 15))*ROWB + ((lane>>4)<<3)*2;
    const uint32_t bBase = B_OFF + (uint32_t)(warp_n*64 + ((lane>>4)&1)*8 + (lane&7))*ROWB + (((lane>>3)&1)<<3)*2;

    float acc[2][8][4];
#pragma unroll
    for(int a=0;a<2;a++)
#pragma unroll
    for(int b=0;b<8;b++)
#pragma unroll
    for(int d=0;d<4;d++) acc[a][b][d]=0.f;

    ISSUE(0); ISSUE(1);
    for(int c=0;c<NCH;c++){
        asm volatile("cp.async.wait_group 1;":::"memory");
        __syncthreads();
        if(c+2<NCH) ISSUE(c+2);
        const uint32_t st = stB[c%NSTG];
        const uint32_t ab = st + aBase, bb = st + bBase;
#pragma unroll
        for(int ks=0; ks<4; ks++){
            uint32_t ah[2][4];
#pragma unroll
            for(int mi=0; mi<2; mi++)
                LDM4(ah[mi], ab + mi*16*ROWB + ks*32);
#pragma unroll
            for(int nj=0; nj<4; nj++){
                uint32_t bt[4];
                LDM4(bt, bb + nj*16*ROWB + ks*32);
#pragma unroll
                for(int mi=0; mi<2; mi++){
                    mma_f16(acc[mi][nj*2+0], ah[mi], &bt[0]);
                    mma_f16(acc[mi][nj*2+1], ah[mi], &bt[2]);
                }
            }
        }
    }
#undef ISSUE
    asm volatile("cp.async.wait_group 0;":::"memory");
    __syncthreads();

    float* w2s   = (float*)(dyn + EP_W2_OFF);
    float* biass = (float*)(dyn + EP_B1_OFF);
    ((float4*)w2s)[tid] = ((const float4*)(W2 + ((size_t)e*H_ + n0)*KK))[tid];
    if(tid < 32) ((float4*)biass)[tid] = ((const float4*)(b1 + (size_t)e*H_ + n0))[tid];
    __syncthreads();

    float* ht = (float*)dyn;
    const int g = lane >> 2, tg2 = (lane & 3)*2;
#pragma unroll
    for(int mi=0; mi<2; mi++){
        int rr = warp_m*32 + mi*16 + g;
#pragma unroll
        for(int ni=0; ni<8; ni++){
            int c0 = warp_n*64 + ni*8 + tg2;
            float2 v0, v1;
            v0.x = fmaxf(acc[mi][ni][0] + biass[c0],   0.f);
            v0.y = fmaxf(acc[mi][ni][1] + biass[c0+1], 0.f);
            v1.x = fmaxf(acc[mi][ni][2] + biass[c0],   0.f);
            v1.y = fmaxf(acc[mi][ni][3] + biass[c0+1], 0.f);
            *(float2*)&ht[(size_t)rr*HTS + c0]     = v0;
            *(float2*)&ht[(size_t)(rr+8)*HTS + c0] = v1;
        }
    }
    __syncthreads();
    {
        const int row = tid >> 1, q = tid & 1;
        const float* hp = &ht[(size_t)row*HTS + q*64];
        const float* wp = &w2s[q*64*8];
        float pl[8];
#pragma unroll
        for(int k=0;k<8;k++) pl[k]=0.f;
#pragma unroll
        for(int cc=0; cc<64; cc++){
            int cr = (cc + q*9) & 63;
            float h = hp[cr];
            const float4* w4 = (const float4*)&wp[cr*8];
            float4 wa = w4[0], wb = w4[1];
            pl[0]=fmaf(h,wa.x,pl[0]); pl[1]=fmaf(h,wa.y,pl[1]);
            pl[2]=fmaf(h,wa.z,pl[2]); pl[3]=fmaf(h,wa.w,pl[3]);
            pl[4]=fmaf(h,wb.x,pl[4]); pl[5]=fmaf(h,wb.y,pl[5]);
            pl[6]=fmaf(h,wb.z,pl[6]); pl[7]=fmaf(h,wb.w,pl[7]);
        }
#pragma unroll
        for(int k=0;k<8;k++) pl[k] += __shfl_xor_sync(0xFFFFFFFFu, pl[k], 1);
        float* dst = gPart + (((size_t)e*20 + nb)*B_ + (m0+row))*KK + q*4;
        *(float4*)dst = make_float4(pl[q*4], pl[q*4+1], pl[q*4+2], pl[q*4+3]);
    }
}

// ---- tail: sum 20 partials per (e,k), +b2, softmax, path products
__global__ __launch_bounds__(256) void tail_kernel(const float* __restrict__ b2,
                                                   float* __restrict__ out){
    const int b = blockIdx.x, tid = threadIdx.x;
    __shared__ float part[180][8];
    __shared__ float logits_s[9][8];
    __shared__ float probs_s[9][8];
    for(int t=tid; t<180; t+=256){
        const float4* src = (const float4*)(gPart + ((size_t)t*B_ + b)*KK);
        *(float4*)&part[t][0] = src[0];
        *(float4*)&part[t][4] = src[1];
    }
    __syncthreads();
    if(tid < 72){
        int e = tid>>3, k = tid&7;
        float s = 0.f;
#pragma unroll
        for(int j=0;j<20;j++) s += part[e*20+j][k];
        float lv = s + b2[tid];
        logits_s[e][k] = lv;
        out[(size_t)B_*73 + ((size_t)e*B_ + b)*KK + k] = lv;
    }
    __syncthreads();
    if(tid < 9){
        float m = -INFINITY;
#pragma unroll
        for(int k=0;k<8;k++) m = fmaxf(m, logits_s[tid][k]);
        float ex[8], s = 0.f;
#pragma unroll
        for(int k=0;k<8;k++){ ex[k] = expf(logits_s[tid][k]-m); s += ex[k]; }
        float inv = 1.f/s;
#pragma unroll
        for(int k=0;k<8;k++) probs_s[tid][k] = ex[k]*inv;
    }
    __syncthreads();
    if(tid < 73){
        float v;
        if(tid==0) v = 1.f;
        else if(tid<9) v = probs_s[0][tid-1];
        else { int t = tid-9; v = probs_s[0][t>>3]*probs_s[1+(t>>3)][t&7]; }
        out[(size_t)b*73 + tid] = v;
    }
}

extern "C" void kernel_launch(void* const* d_in, const int* in_sizes, int n_in,
                              void* d_out, int out_size){
    const float* x  = (const float*)d_in[0];
    const float* W1 = (const float*)d_in[1];
    const float* b1 = (const float*)d_in[2];
    const float* W2 = (const float*)d_in[3];
    const float* b2 = (const float*)d_in[4];
    float* out = (float*)d_out;

    cudaFuncSetAttribute(fused_kernel, cudaFuncAttributeMaxDynamicSharedMemorySize, DYN_BYTES);

    reset_kernel<<<1, 256>>>();
    fused_kernel<<<NXC + 4320, 256, DYN_BYTES>>>(W1, W2, b1, x);
    tail_kernel<<<B_, 256>>>(b2, out);
}

// round 15
// speedup vs baseline: 1.3660x; 1.3660x over previous
#include <cuda_runtime.h>
#include <cuda_fp16.h>
#include <math.h>
#include <stdint.h>

#define B_  512
#define F_  1280
#define H_  2560
#define KK  8
#define E_  9

#define CH   64
#define NCH  (F_/CH)                // 20
#define SAE  72
#define ROWB (SAE*2)                // 144
#define ABUF_BYTES (128*ROWB)
#define BBUF_BYTES (128*ROWB)
#define STAGE_BYTES (ABUF_BYTES+BBUF_BYTES)  // 36864
#define A_OFF 0
#define B_OFF ABUF_BYTES
#define NSTG 3
#define DYN_BYTES (NSTG*STAGE_BYTES)  // 110592 -> 2 CTAs/SM
#define HTS 130
#define EP_W2_OFF  66560
#define EP_B1_OFF  70656

#define NXC 160                     // conv_x bids in merged conv launch

__device__ __half gW[(size_t)E_*H_*F_];       // W1^T fp16 [e][n][k]
__device__ __half gX[(size_t)B_*F_];          // x fp16 [b][k]
__device__ float gPart[(size_t)B_*180*KK];    // [b][t=e*20+nb][8]  (tail-coalesced)

__device__ __forceinline__ uint32_t smem_u32(const void* p){
    uint32_t a; asm("{ .reg .u64 t; cvta.to.shared.u64 t, %1; cvt.u32.u64 %0, t; }":"=r"(a):"l"(p)); return a;
}
#define CP16(dst,src) asm volatile("cp.async.cg.shared.global [%0], [%1], 16;"::"r"(dst),"l"(src):"memory")
#define LDM4(r,addr) asm volatile("ldmatrix.sync.aligned.m8n8.x4.shared.b16 {%0,%1,%2,%3}, [%4];" \
    : "=r"((r)[0]),"=r"((r)[1]),"=r"((r)[2]),"=r"((r)[3]) : "r"(addr))
__device__ __forceinline__ void mma_f16(float* c, const uint32_t* a, const uint32_t* b){
    asm volatile("mma.sync.aligned.m16n8k16.row.col.f32.f16.f16.f32 "
        "{%0,%1,%2,%3},{%4,%5,%6,%7},{%8,%9},{%0,%1,%2,%3};"
        : "+f"(c[0]),"+f"(c[1]),"+f"(c[2]),"+f"(c[3])
        : "r"(a[0]),"r"(a[1]),"r"(a[2]),"r"(a[3]),"r"(b[0]),"r"(b[1]));
}
__device__ __forceinline__ uint32_t pack2(float a, float b){
    __half2 h = __floats2half2_rn(a, b);
    return *reinterpret_cast<uint32_t*>(&h);
}

// ---- merged conversion: bids [0,NXC) convert x; bids [NXC, NXC+3600) convert W1 tiles
__global__ __launch_bounds__(256) void conv_all_kernel(const float* __restrict__ x,
                                                       const float* __restrict__ W1){
    __shared__ float s[64][129];
    int bid = blockIdx.x;
    const int tid = threadIdx.x;

    if(bid < NXC){
        // x -> fp16: 163840 float4s / 160 CTAs = 4/thread
        int base = bid*1024 + tid;
#pragma unroll
        for(int u=0; u<4; u++){
            int i = base + u*256;
            float4 v = ((const float4*)x)[i];
            uint2 o;
            o.x = pack2(v.x, v.y);
            o.y = pack2(v.z, v.w);
            ((uint2*)gX)[i] = o;
        }
        return;
    }
    bid -= NXC;

    // W1 [e][k][n] -> W1^T fp16 [e][n][k]; tile = 64k x 128n
    int nb = bid % 20, kc = (bid/20) % 20, e = bid/400;
    const float* src = W1 + ((size_t)e*F_ + (size_t)kc*64)*H_ + (size_t)nb*128;
    for(int i=tid; i<64*128; i+=256){
        int kk = i>>7, r = i&127;
        s[kk][r] = src[(size_t)kk*H_ + r];
    }
    __syncthreads();
    int kg = tid & 7;
    int rbase = tid >> 3;
#pragma unroll
    for(int u=0; u<4; u++){
        int row = u*32 + rbase;
        uint4 o;
        o.x = pack2(s[kg*8+0][row], s[kg*8+1][row]);
        o.y = pack2(s[kg*8+2][row], s[kg*8+3][row]);
        o.z = pack2(s[kg*8+4][row], s[kg*8+5][row]);
        o.w = pack2(s[kg*8+6][row], s[kg*8+7][row]);
        size_t off = (size_t)e*H_*F_ + (size_t)(nb*128+row)*F_ + kc*64 + kg*8;
        *(uint4*)(gW+off) = o;
    }
}

// ---- GEMM1 + fused bias/ReLU + GEMM2 partials (R9 body; gPart layout transposed).
// grid (4 mb, 20 nb, 9 e) = 720 CTAs, 256 threads, 2 CTAs/SM.
__global__ __launch_bounds__(256,2) void gemm_kernel(const float* __restrict__ W2,
                                                     const float* __restrict__ b1){
    extern __shared__ char dyn[];
    const int tid = threadIdx.x, lane = tid & 31, wid = tid >> 5;
    const int warp_m = wid & 3, warp_n = wid >> 2;
    const int m0 = blockIdx.x*128, n0 = blockIdx.y*128, e = blockIdx.z;
    const uint32_t dynU = smem_u32(dyn);

    const int seg = tid & 7;
    const __half* gA = gX + (size_t)m0*F_;
    const __half* gB = gW + ((size_t)e*H_ + n0)*F_;
    const int r0 = tid>>3, r1 = (tid+256)>>3, r2 = (tid+512)>>3, r3 = (tid+768)>>3;

    uint32_t stB[NSTG];
#pragma unroll
    for(int s=0;s<NSTG;s++) stB[s] = dynU + s*STAGE_BYTES;

#define ISSUE(c) do{ \
    uint32_t st_ = stB[(c)%NSTG]; int ko_ = (c)*CH + seg*8; \
    CP16(st_+A_OFF + r0*ROWB + seg*16, gA + (size_t)r0*F_ + ko_); \
    CP16(st_+A_OFF + r1*ROWB + seg*16, gA + (size_t)r1*F_ + ko_); \
    CP16(st_+A_OFF + r2*ROWB + seg*16, gA + (size_t)r2*F_ + ko_); \
    CP16(st_+A_OFF + r3*ROWB + seg*16, gA + (size_t)r3*F_ + ko_); \
    CP16(st_+B_OFF + r0*ROWB + seg*16, gB + (size_t)r0*F_ + ko_); \
    CP16(st_+B_OFF + r1*ROWB + seg*16, gB + (size_t)r1*F_ + ko_); \
    CP16(st_+B_OFF + r2*ROWB + seg*16, gB + (size_t)r2*F_ + ko_); \
    CP16(st_+B_OFF + r3*ROWB + seg*16, gB + (size_t)r3*F_ + ko_); \
    asm volatile("cp.async.commit_group;":::"memory"); }while(0)

    const uint32_t aBase = A_OFF + (uint32_t)(warp_m*32 + (lane & 15))*ROWB + ((lane>>4)<<3)*2;
    const uint32_t bBase = B_OFF + (uint32_t)(warp_n*64 + ((lane>>4)&1)*8 + (lane&7))*ROWB + (((lane>>3)&1)<<3)*2;

    float acc[2][8][4];
#pragma unroll
    for(int a=0;a<2;a++)
#pragma unroll
    for(int b=0;b<8;b++)
#pragma unroll
    for(int d=0;d<4;d++) acc[a][b][d]=0.f;

    ISSUE(0); ISSUE(1);
    for(int c=0;c<NCH;c++){
        asm volatile("cp.async.wait_group 1;":::"memory");
        __syncthreads();
        if(c+2<NCH) ISSUE(c+2);
        const uint32_t st = stB[c%NSTG];
        const uint32_t ab = st + aBase, bb = st + bBase;
#pragma unroll
        for(int ks=0; ks<4; ks++){
            uint32_t ah[2][4];
#pragma unroll
            for(int mi=0; mi<2; mi++)
                LDM4(ah[mi], ab + mi*16*ROWB + ks*32);
#pragma unroll
            for(int nj=0; nj<4; nj++){
                uint32_t bt[4];
                LDM4(bt, bb + nj*16*ROWB + ks*32);
#pragma unroll
                for(int mi=0; mi<2; mi++){
                    mma_f16(acc[mi][nj*2+0], ah[mi], &bt[0]);
                    mma_f16(acc[mi][nj*2+1], ah[mi], &bt[2]);
                }
            }
        }
    }
#undef ISSUE
    asm volatile("cp.async.wait_group 0;":::"memory");
    __syncthreads();

    float* w2s   = (float*)(dyn + EP_W2_OFF);
    float* biass = (float*)(dyn + EP_B1_OFF);
    ((float4*)w2s)[tid] = ((const float4*)(W2 + ((size_t)e*H_ + n0)*KK))[tid];
    if(tid < 32) ((float4*)biass)[tid] = ((const float4*)(b1 + (size_t)e*H_ + n0))[tid];
    __syncthreads();

    float* ht = (float*)dyn;
    const int g = lane >> 2, tg2 = (lane & 3)*2;
#pragma unroll
    for(int mi=0; mi<2; mi++){
        int rr = warp_m*32 + mi*16 + g;
#pragma unroll
        for(int ni=0; ni<8; ni++){
            int c0 = warp_n*64 + ni*8 + tg2;
            float2 v0, v1;
            v0.x = fmaxf(acc[mi][ni][0] + biass[c0],   0.f);
            v0.y = fmaxf(acc[mi][ni][1] + biass[c0+1], 0.f);
            v1.x = fmaxf(acc[mi][ni][2] + biass[c0],   0.f);
            v1.y = fmaxf(acc[mi][ni][3] + biass[c0+1], 0.f);
            *(float2*)&ht[(size_t)rr*HTS + c0]     = v0;
            *(float2*)&ht[(size_t)(rr+8)*HTS + c0] = v1;
        }
    }
    __syncthreads();
    {
        const int row = tid >> 1, q = tid & 1;
        const float* hp = &ht[(size_t)row*HTS + q*64];
        const float* wp = &w2s[q*64*8];
        float pl[8];
#pragma unroll
        for(int k=0;k<8;k++) pl[k]=0.f;
#pragma unroll
        for(int cc=0; cc<64; cc++){
            int cr = (cc + q*9) & 63;
            float h = hp[cr];
            const float4* w4 = (const float4*)&wp[cr*8];
            float4 wa = w4[0], wb = w4[1];
            pl[0]=fmaf(h,wa.x,pl[0]); pl[1]=fmaf(h,wa.y,pl[1]);
            pl[2]=fmaf(h,wa.z,pl[2]); pl[3]=fmaf(h,wa.w,pl[3]);
            pl[4]=fmaf(h,wb.x,pl[4]); pl[5]=fmaf(h,wb.y,pl[5]);
            pl[6]=fmaf(h,wb.z,pl[6]); pl[7]=fmaf(h,wb.w,pl[7]);
        }
#pragma unroll
        for(int k=0;k<8;k++) pl[k] += __shfl_xor_sync(0xFFFFFFFFu, pl[k], 1);
        // transposed layout: [b][t][8], t = e*20 + nb
        float* dst = gPart + (((size_t)(m0+row)*180) + (e*20 + blockIdx.y))*KK + q*4;
        *(float4*)dst = make_float4(pl[q*4], pl[q*4+1], pl[q*4+2], pl[q*4+3]);
    }
}

// ---- tail: sum 20 partials per (e,k), +b2, softmax, path products (coalesced reads)
__global__ __launch_bounds__(256) void tail_kernel(const float* __restrict__ b2,
                                                   float* __restrict__ out){
    const int b = blockIdx.x, tid = threadIdx.x;
    __shared__ float part[180][8];
    __shared__ float logits_s[9][8];
    __shared__ float probs_s[9][8];
    // contiguous 5760B block per batch row
    {
        const float4* src = (const float4*)(gPart + (size_t)b*180*KK);
        float4* dst4 = (float4*)&part[0][0];
        for(int i=tid; i<180*2; i+=256) dst4[i] = src[i];
    }
    __syncthreads();
    if(tid < 72){
        int e = tid>>3, k = tid&7;
        float s = 0.f;
#pragma unroll
        for(int j=0;j<20;j++) s += part[e*20+j][k];
        float lv = s + b2[tid];
        logits_s[e][k] = lv;
        out[(size_t)B_*73 + ((size_t)e*B_ + b)*KK + k] = lv;
    }
    __syncthreads();
    if(tid < 9){
        float m = -INFINITY;
#pragma unroll
        for(int k=0;k<8;k++) m = fmaxf(m, logits_s[tid][k]);
        float ex[8], s = 0.f;
#pragma unroll
        for(int k=0;k<8;k++){ ex[k] = expf(logits_s[tid][k]-m); s += ex[k]; }
        float inv = 1.f/s;
#pragma unroll
        for(int k=0;k<8;k++) probs_s[tid][k] = ex[k]*inv;
    }
    __syncthreads();
    if(tid < 73){
        float v;
        if(tid==0) v = 1.f;
        else if(tid<9) v = probs_s[0][tid-1];
        else { int t = tid-9; v = probs_s[0][t>>3]*probs_s[1+(t>>3)][t&7]; }
        out[(size_t)b*73 + tid] = v;
    }
}

extern "C" void kernel_launch(void* const* d_in, const int* in_sizes, int n_in,
                              void* d_out, int out_size){
    const float* x  = (const float*)d_in[0];
    const float* W1 = (const float*)d_in[1];
    const float* b1 = (const float*)d_in[2];
    const float* W2 = (const float*)d_in[3];
    const float* b2 = (const float*)d_in[4];
    float* out = (float*)d_out;

    cudaFuncSetAttribute(gemm_kernel, cudaFuncAttributeMaxDynamicSharedMemorySize, DYN_BYTES);

    conv_all_kernel<<<NXC + 3600, 256>>>(x, W1);
    dim3 grid(4, 20, 9);
    gemm_kernel<<<grid, 256, DYN_BYTES>>>(W2, b1);
    tail_kernel<<<B_, 256>>>(b2, out);
}

// round 16
// speedup vs baseline: 1.4287x; 1.0459x over previous
#include <cuda_runtime.h>
#include <cuda_fp16.h>
#include <math.h>
#include <stdint.h>

#define B_  512
#define F_  1280
#define H_  2560
#define KK  8
#define E_  9

#define CH   64
#define NCH  (F_/CH)                // 20
#define SAE  72
#define ROWB (SAE*2)                // 144
#define ABUF_BYTES (128*ROWB)
#define BBUF_BYTES (128*ROWB)
#define STAGE_BYTES (ABUF_BYTES+BBUF_BYTES)  // 36864
#define A_OFF 0
#define B_OFF ABUF_BYTES
#define NSTG 3
#define DYN_BYTES (NSTG*STAGE_BYTES)  // 110592 -> 2 CTAs/SM
#define HTS 130
#define EP_W2_OFF  66560
#define EP_B1_OFF  70656

#define NXC 160                     // conv_x bids in merged conv launch

__device__ __half gW[(size_t)E_*H_*F_];       // W1^T fp16 [e][n][k]
__device__ __half gX[(size_t)B_*F_];          // x fp16 [b][k]
__device__ float gPart[(size_t)B_*180*KK];    // [b][t=e*20+nb][8]

__device__ __forceinline__ uint32_t smem_u32(const void* p){
    uint32_t a; asm("{ .reg .u64 t; cvta.to.shared.u64 t, %1; cvt.u32.u64 %0, t; }":"=r"(a):"l"(p)); return a;
}
#define CP16(dst,src) asm volatile("cp.async.cg.shared.global [%0], [%1], 16;"::"r"(dst),"l"(src):"memory")
#define LDM4(r,addr) asm volatile("ldmatrix.sync.aligned.m8n8.x4.shared.b16 {%0,%1,%2,%3}, [%4];" \
    : "=r"((r)[0]),"=r"((r)[1]),"=r"((r)[2]),"=r"((r)[3]) : "r"(addr))
__device__ __forceinline__ void mma_f16(float* c, const uint32_t* a, const uint32_t* b){
    asm volatile("mma.sync.aligned.m16n8k16.row.col.f32.f16.f16.f32 "
        "{%0,%1,%2,%3},{%4,%5,%6,%7},{%8,%9},{%0,%1,%2,%3};"
        : "+f"(c[0]),"+f"(c[1]),"+f"(c[2]),"+f"(c[3])
        : "r"(a[0]),"r"(a[1]),"r"(a[2]),"r"(a[3]),"r"(b[0]),"r"(b[1]));
}
__device__ __forceinline__ uint32_t pack2(float a, float b){
    __half2 h = __floats2half2_rn(a, b);
    return *reinterpret_cast<uint32_t*>(&h);
}

// ---- merged conversion: bids [0,NXC) convert x; bids [NXC,...) convert W1 tiles.
// W1 tile path: float4 loads, XOR-swizzled smem (conflict-free both phases).
__global__ __launch_bounds__(256) void conv_all_kernel(const float* __restrict__ x,
                                                       const float* __restrict__ W1){
    __shared__ float s[64*128];     // physical col = c ^ (4*(kk>>3))
    int bid = blockIdx.x;
    const int tid = threadIdx.x;

    if(bid < NXC){
        int base = bid*1024 + tid;
#pragma unroll
        for(int u=0; u<4; u++){
            int i = base + u*256;
            float4 v = ((const float4*)x)[i];
            uint2 o;
            o.x = pack2(v.x, v.y);
            o.y = pack2(v.z, v.w);
            ((uint2*)gX)[i] = o;
        }
        return;
    }
    bid -= NXC;

    int nb = bid % 20, kc = (bid/20) % 20, e = bid/400;
    const float* src = W1 + ((size_t)e*F_ + (size_t)kc*64)*H_ + (size_t)nb*128;

    // load: 64 rows x 32 float4; one warp covers one row per iteration
#pragma unroll
    for(int it=0; it<8; it++){
        int i  = tid + it*256;
        int kk = i >> 5;             // 0..63
        int c4 = i & 31;             // float4 col
        float4 v = *(const float4*)&src[(size_t)kk*H_ + c4*4];
        int swz = 4*(kk>>3);         // 0,4,...,28 (mod-4 == 0 -> float4-safe XOR)
        *(float4*)&s[kk*128 + ((c4*4) ^ swz)] = v;
    }
    __syncthreads();

    // transpose+convert: thread (kg=tid&7, rbase=tid>>3) handles k-group kg, rows u*32+rbase
    int kg = tid & 7;
    int rbase = tid >> 3;
    const int swz = 4*kg;
#pragma unroll
    for(int u=0; u<4; u++){
        int row = u*32 + rbase;
        float f[8];
#pragma unroll
        for(int j=0;j<8;j++) f[j] = s[(kg*8+j)*128 + (row ^ swz)];
        uint4 o;
        o.x = pack2(f[0], f[1]);
        o.y = pack2(f[2], f[3]);
        o.z = pack2(f[4], f[5]);
        o.w = pack2(f[6], f[7]);
        size_t off = (size_t)e*H_*F_ + (size_t)(nb*128+row)*F_ + kc*64 + kg*8;
        *(uint4*)(gW+off) = o;
    }
}

// ---- GEMM1 + fused bias/ReLU + GEMM2 partials (R15 body, unchanged).
__global__ __launch_bounds__(256,2) void gemm_kernel(const float* __restrict__ W2,
                                                     const float* __restrict__ b1){
    extern __shared__ char dyn[];
    const int tid = threadIdx.x, lane = tid & 31, wid = tid >> 5;
    const int warp_m = wid & 3, warp_n = wid >> 2;
    const int m0 = blockIdx.x*128, n0 = blockIdx.y*128, e = blockIdx.z;
    const uint32_t dynU = smem_u32(dyn);

    const int seg = tid & 7;
    const __half* gA = gX + (size_t)m0*F_;
    const __half* gB = gW + ((size_t)e*H_ + n0)*F_;
    const int r0 = tid>>3, r1 = (tid+256)>>3, r2 = (tid+512)>>3, r3 = (tid+768)>>3;

    uint32_t stB[NSTG];
#pragma unroll
    for(int s=0;s<NSTG;s++) stB[s] = dynU + s*STAGE_BYTES;

#define ISSUE(c) do{ \
    uint32_t st_ = stB[(c)%NSTG]; int ko_ = (c)*CH + seg*8; \
    CP16(st_+A_OFF + r0*ROWB + seg*16, gA + (size_t)r0*F_ + ko_); \
    CP16(st_+A_OFF + r1*ROWB + seg*16, gA + (size_t)r1*F_ + ko_); \
    CP16(st_+A_OFF + r2*ROWB + seg*16, gA + (size_t)r2*F_ + ko_); \
    CP16(st_+A_OFF + r3*ROWB + seg*16, gA + (size_t)r3*F_ + ko_); \
    CP16(st_+B_OFF + r0*ROWB + seg*16, gB + (size_t)r0*F_ + ko_); \
    CP16(st_+B_OFF + r1*ROWB + seg*16, gB + (size_t)r1*F_ + ko_); \
    CP16(st_+B_OFF + r2*ROWB + seg*16, gB + (size_t)r2*F_ + ko_); \
    CP16(st_+B_OFF + r3*ROWB + seg*16, gB + (size_t)r3*F_ + ko_); \
    asm volatile("cp.async.commit_group;":::"memory"); }while(0)

    const uint32_t aBase = A_OFF + (uint32_t)(warp_m*32 + (lane & 15))*ROWB + ((lane>>4)<<3)*2;
    const uint32_t bBase = B_OFF + (uint32_t)(warp_n*64 + ((lane>>4)&1)*8 + (lane&7))*ROWB + (((lane>>3)&1)<<3)*2;

    float acc[2][8][4];
#pragma unroll
    for(int a=0;a<2;a++)
#pragma unroll
    for(int b=0;b<8;b++)
#pragma unroll
    for(int d=0;d<4;d++) acc[a][b][d]=0.f;

    ISSUE(0); ISSUE(1);
    for(int c=0;c<NCH;c++){
        asm volatile("cp.async.wait_group 1;":::"memory");
        __syncthreads();
        if(c+2<NCH) ISSUE(c+2);
        const uint32_t st = stB[c%NSTG];
        const uint32_t ab = st + aBase, bb = st + bBase;
#pragma unroll
        for(int ks=0; ks<4; ks++){
            uint32_t ah[2][4];
#pragma unroll
            for(int mi=0; mi<2; mi++)
                LDM4(ah[mi], ab + mi*16*ROWB + ks*32);
#pragma unroll
            for(int nj=0; nj<4; nj++){
                uint32_t bt[4];
                LDM4(bt, bb + nj*16*ROWB + ks*32);
#pragma unroll
                for(int mi=0; mi<2; mi++){
                    mma_f16(acc[mi][nj*2+0], ah[mi], &bt[0]);
                    mma_f16(acc[mi][nj*2+1], ah[mi], &bt[2]);
                }
            }
        }
    }
#undef ISSUE
    asm volatile("cp.async.wait_group 0;":::"memory");
    __syncthreads();

    float* w2s   = (float*)(dyn + EP_W2_OFF);
    float* biass = (float*)(dyn + EP_B1_OFF);
    ((float4*)w2s)[tid] = ((const float4*)(W2 + ((size_t)e*H_ + n0)*KK))[tid];
    if(tid < 32) ((float4*)biass)[tid] = ((const float4*)(b1 + (size_t)e*H_ + n0))[tid];
    __syncthreads();

    float* ht = (float*)dyn;
    const int g = lane >> 2, tg2 = (lane & 3)*2;
#pragma unroll
    for(int mi=0; mi<2; mi++){
        int rr = warp_m*32 + mi*16 + g;
#pragma unroll
        for(int ni=0; ni<8; ni++){
            int c0 = warp_n*64 + ni*8 + tg2;
            float2 v0, v1;
            v0.x = fmaxf(acc[mi][ni][0] + biass[c0],   0.f);
            v0.y = fmaxf(acc[mi][ni][1] + biass[c0+1], 0.f);
            v1.x = fmaxf(acc[mi][ni][2] + biass[c0],   0.f);
            v1.y = fmaxf(acc[mi][ni][3] + biass[c0+1], 0.f);
            *(float2*)&ht[(size_t)rr*HTS + c0]     = v0;
            *(float2*)&ht[(size_t)(rr+8)*HTS + c0] = v1;
        }
    }
    __syncthreads();
    {
        const int row = tid >> 1, q = tid & 1;
        const float* hp = &ht[(size_t)row*HTS + q*64];
        const float* wp = &w2s[q*64*8];
        float pl[8];
#pragma unroll
        for(int k=0;k<8;k++) pl[k]=0.f;
#pragma unroll
        for(int cc=0; cc<64; cc++){
            int cr = (cc + q*9) & 63;
            float h = hp[cr];
            const float4* w4 = (const float4*)&wp[cr*8];
            float4 wa = w4[0], wb = w4[1];
            pl[0]=fmaf(h,wa.x,pl[0]); pl[1]=fmaf(h,wa.y,pl[1]);
            pl[2]=fmaf(h,wa.z,pl[2]); pl[3]=fmaf(h,wa.w,pl[3]);
            pl[4]=fmaf(h,wb.x,pl[4]); pl[5]=fmaf(h,wb.y,pl[5]);
            pl[6]=fmaf(h,wb.z,pl[6]); pl[7]=fmaf(h,wb.w,pl[7]);
        }
#pragma unroll
        for(int k=0;k<8;k++) pl[k] += __shfl_xor_sync(0xFFFFFFFFu, pl[k], 1);
        float* dst = gPart + (((size_t)(m0+row)*180) + (e*20 + blockIdx.y))*KK + q*4;
        *(float4*)dst = make_float4(pl[q*4], pl[q*4+1], pl[q*4+2], pl[q*4+3]);
    }
}

// ---- tail (R15 body, unchanged)
__global__ __launch_bounds__(256) void tail_kernel(const float* __restrict__ b2,
                                                   float* __restrict__ out){
    const int b = blockIdx.x, tid = threadIdx.x;
    __shared__ float part[180][8];
    __shared__ float logits_s[9][8];
    __shared__ float probs_s[9][8];
    {
        const float4* src = (const float4*)(gPart + (size_t)b*180*KK);
        float4* dst4 = (float4*)&part[0][0];
        for(int i=tid; i<180*2; i+=256) dst4[i] = src[i];
    }
    __syncthreads();
    if(tid < 72){
        int e = tid>>3, k = tid&7;
        float s = 0.f;
#pragma unroll
        for(int j=0;j<20;j++) s += part[e*20+j][k];
        float lv = s + b2[tid];
        logits_s[e][k] = lv;
        out[(size_t)B_*73 + ((size_t)e*B_ + b)*KK + k] = lv;
    }
    __syncthreads();
    if(tid < 9){
        float m = -INFINITY;
#pragma unroll
        for(int k=0;k<8;k++) m = fmaxf(m, logits_s[tid][k]);
        float ex[8], s = 0.f;
#pragma unroll
        for(int k=0;k<8;k++){ ex[k] = expf(logits_s[tid][k]-m); s += ex[k]; }
        float inv = 1.f/s;
#pragma unroll
        for(int k=0;k<8;k++) probs_s[tid][k] = ex[k]*inv;
    }
    __syncthreads();
    if(tid < 73){
        float v;
        if(tid==0) v = 1.f;
        else if(tid<9) v = probs_s[0][tid-1];
        else { int t = tid-9; v = probs_s[0][t>>3]*probs_s[1+(t>>3)][t&7]; }
        out[(size_t)b*73 + tid] = v;
    }
}

extern "C" void kernel_launch(void* const* d_in, const int* in_sizes, int n_in,
                              void* d_out, int out_size){
    const float* x  = (const float*)d_in[0];
    const float* W1 = (const float*)d_in[1];
    const float* b1 = (const float*)d_in[2];
    const float* W2 = (const float*)d_in[3];
    const float* b2 = (const float*)d_in[4];
    float* out = (float*)d_out;

    cudaFuncSetAttribute(gemm_kernel, cudaFuncAttributeMaxDynamicSharedMemorySize, DYN_BYTES);

    conv_all_kernel<<<NXC + 3600, 256>>>(x, W1);
    dim3 grid(4, 20, 9);
    gemm_kernel<<<grid, 256, DYN_BYTES>>>(W2, b1);
    tail_kernel<<<B_, 256>>>(b2, out);
}

// round 17
// speedup vs baseline: 1.4849x; 1.0393x over previous
#include <cuda_runtime.h>
#include <cuda_fp16.h>
#include <math.h>
#include <stdint.h>

#define B_  512
#define F_  1280
#define H_  2560
#define KK  8
#define E_  9

#define CH   64
#define NCH  (F_/CH)                // 20
#define SAE  72
#define ROWB (SAE*2)                // 144
#define ABUF_BYTES (128*ROWB)
#define BBUF_BYTES (128*ROWB)
#define STAGE_BYTES (ABUF_BYTES+BBUF_BYTES)  // 36864
#define A_OFF 0
#define B_OFF ABUF_BYTES
#define NSTG 3
#define DYN_BYTES (NSTG*STAGE_BYTES)  // 110592 -> 2 CTAs/SM
#define HTS 130
#define EP_W2_OFF  66560
#define EP_B1_OFF  70656

#define NXC 160                     // x-conversion bids (lead the grid)
#define NWC 360                     // W1-conversion CTAs: (e, nb, half), 10 tiles each
#define CONV_DYN 65536              // 2 x 32KB tile buffers

__device__ __half gW[(size_t)E_*H_*F_];       // W1^T fp16 [e][n][k]
__device__ __half gX[(size_t)B_*F_];          // x fp16 [b][k]
__device__ float gPart[(size_t)B_*180*KK];    // [b][t=e*20+nb][8]

__device__ __forceinline__ uint32_t smem_u32(const void* p){
    uint32_t a; asm("{ .reg .u64 t; cvta.to.shared.u64 t, %1; cvt.u32.u64 %0, t; }":"=r"(a):"l"(p)); return a;
}
#define CP16(dst,src) asm volatile("cp.async.cg.shared.global [%0], [%1], 16;"::"r"(dst),"l"(src):"memory")
#define LDM4(r,addr) asm volatile("ldmatrix.sync.aligned.m8n8.x4.shared.b16 {%0,%1,%2,%3}, [%4];" \
    : "=r"((r)[0]),"=r"((r)[1]),"=r"((r)[2]),"=r"((r)[3]) : "r"(addr))
__device__ __forceinline__ void mma_f16(float* c, const uint32_t* a, const uint32_t* b){
    asm volatile("mma.sync.aligned.m16n8k16.row.col.f32.f16.f16.f32 "
        "{%0,%1,%2,%3},{%4,%5,%6,%7},{%8,%9},{%0,%1,%2,%3};"
        : "+f"(c[0]),"+f"(c[1]),"+f"(c[2]),"+f"(c[3])
        : "r"(a[0]),"r"(a[1]),"r"(a[2]),"r"(a[3]),"r"(b[0]),"r"(b[1]));
}
__device__ __forceinline__ uint32_t pack2(float a, float b){
    __half2 h = __floats2half2_rn(a, b);
    return *reinterpret_cast<uint32_t*>(&h);
}

// ---- merged conversion. bids [0,NXC): x -> fp16. bids [NXC, NXC+NWC): W1 tiles,
// 10 tiles per CTA, cp.async double-buffered (loads of t+1 overlap store of t).
__global__ __launch_bounds__(256) void conv_all_kernel(const float* __restrict__ x,
                                                       const float* __restrict__ W1){
    extern __shared__ float cs[];   // 2 x 8192 floats
    int bid = blockIdx.x;
    const int tid = threadIdx.x;

    if(bid < NXC){
        int base = bid*1024 + tid;
#pragma unroll
        for(int u=0; u<4; u++){
            int i = base + u*256;
            float4 v = ((const float4*)x)[i];
            uint2 o;
            o.x = pack2(v.x, v.y);
            o.y = pack2(v.z, v.w);
            ((uint2*)gX)[i] = o;
        }
        return;
    }
    bid -= NXC;

    const int e = bid/40, rem = bid%40, nb = rem%20, half = rem/20;  // half in {0,1}
    const uint32_t csU = smem_u32(cs);

    // per-thread cp.async mapping (8 x 16B per tile): i = tid + j*256
    // kk = i>>5 (0..63), c4 = i&31 ; dst byte = kk*512 + ((c4*16) ^ (16*(kk>>3)))
    // per-thread store mapping: kg = tid&7, rbase = tid>>3
    const int kg = tid & 7, rbase = tid >> 3;
    const int swz = 4*kg;

#define CONV_ISSUE(t) do{ \
    uint32_t bufU = csU + ((t)&1)*32768; \
    const float* srcT = W1 + ((size_t)e*F_ + (size_t)(half*10+(t))*64)*H_ + (size_t)nb*128; \
    _Pragma("unroll") \
    for(int j=0;j<8;j++){ \
        int i  = tid + j*256; \
        int kk = i >> 5, c4 = i & 31; \
        CP16(bufU + kk*512 + ((c4*16) ^ (16*(kk>>3))), srcT + (size_t)kk*H_ + c4*4); \
    } \
    asm volatile("cp.async.commit_group;":::"memory"); }while(0)

    CONV_ISSUE(0);
    for(int t=0; t<10; t++){
        if(t+1 < 10){
            CONV_ISSUE(t+1);
            asm volatile("cp.async.wait_group 1;":::"memory");
        } else {
            asm volatile("cp.async.wait_group 0;":::"memory");
        }
        __syncthreads();
        const float* buf = cs + (t&1)*8192;
        const int kc = half*10 + t;
#pragma unroll
        for(int u=0; u<4; u++){
            int row = u*32 + rbase;
            float f[8];
#pragma unroll
            for(int j=0;j<8;j++) f[j] = buf[(kg*8+j)*128 + (row ^ swz)];
            uint4 o;
            o.x = pack2(f[0], f[1]);
            o.y = pack2(f[2], f[3]);
            o.z = pack2(f[4], f[5]);
            o.w = pack2(f[6], f[7]);
            size_t off = (size_t)e*H_*F_ + (size_t)(nb*128+row)*F_ + kc*64 + kg*8;
            *(uint4*)(gW+off) = o;
        }
        __syncthreads();   // buffer t%2 free for reuse at t+2
    }
#undef CONV_ISSUE
}

// ---- GEMM1 + fused bias/ReLU + GEMM2 partials (R16 body, unchanged).
__global__ __launch_bounds__(256,2) void gemm_kernel(const float* __restrict__ W2,
                                                     const float* __restrict__ b1){
    extern __shared__ char dyn[];
    const int tid = threadIdx.x, lane = tid & 31, wid = tid >> 5;
    const int warp_m = wid & 3, warp_n = wid >> 2;
    const int m0 = blockIdx.x*128, n0 = blockIdx.y*128, e = blockIdx.z;
    const uint32_t dynU = smem_u32(dyn);

    const int seg = tid & 7;
    const __half* gA = gX + (size_t)m0*F_;
    const __half* gB = gW + ((size_t)e*H_ + n0)*F_;
    const int r0 = tid>>3, r1 = (tid+256)>>3, r2 = (tid+512)>>3, r3 = (tid+768)>>3;

    uint32_t stB[NSTG];
#pragma unroll
    for(int s=0;s<NSTG;s++) stB[s] = dynU + s*STAGE_BYTES;

#define ISSUE(c) do{ \
    uint32_t st_ = stB[(c)%NSTG]; int ko_ = (c)*CH + seg*8; \
    CP16(st_+A_OFF + r0*ROWB + seg*16, gA + (size_t)r0*F_ + ko_); \
    CP16(st_+A_OFF + r1*ROWB + seg*16, gA + (size_t)r1*F_ + ko_); \
    CP16(st_+A_OFF + r2*ROWB + seg*16, gA + (size_t)r2*F_ + ko_); \
    CP16(st_+A_OFF + r3*ROWB + seg*16, gA + (size_t)r3*F_ + ko_); \
    CP16(st_+B_OFF + r0*ROWB + seg*16, gB + (size_t)r0*F_ + ko_); \
    CP16(st_+B_OFF + r1*ROWB + seg*16, gB + (size_t)r1*F_ + ko_); \
    CP16(st_+B_OFF + r2*ROWB + seg*16, gB + (size_t)r2*F_ + ko_); \
    CP16(st_+B_OFF + r3*ROWB + seg*16, gB + (size_t)r3*F_ + ko_); \
    asm volatile("cp.async.commit_group;":::"memory"); }while(0)

    const uint32_t aBase = A_OFF + (uint32_t)(warp_m*32 + (lane & 15))*ROWB + ((lane>>4)<<3)*2;
    const uint32_t bBase = B_OFF + (uint32_t)(warp_n*64 + ((lane>>4)&1)*8 + (lane&7))*ROWB + (((lane>>3)&1)<<3)*2;

    float acc[2][8][4];
#pragma unroll
    for(int a=0;a<2;a++)
#pragma unroll
    for(int b=0;b<8;b++)
#pragma unroll
    for(int d=0;d<4;d++) acc[a][b][d]=0.f;

    ISSUE(0); ISSUE(1);
    for(int c=0;c<NCH;c++){
        asm volatile("cp.async.wait_group 1;":::"memory");
        __syncthreads();
        if(c+2<NCH) ISSUE(c+2);
        const uint32_t st = stB[c%NSTG];
        const uint32_t ab = st + aBase, bb = st + bBase;
#pragma unroll
        for(int ks=0; ks<4; ks++){
            uint32_t ah[2][4];
#pragma unroll
            for(int mi=0; mi<2; mi++)
                LDM4(ah[mi], ab + mi*16*ROWB + ks*32);
#pragma unroll
            for(int nj=0; nj<4; nj++){
                uint32_t bt[4];
                LDM4(bt, bb + nj*16*ROWB + ks*32);
#pragma unroll
                for(int mi=0; mi<2; mi++){
                    mma_f16(acc[mi][nj*2+0], ah[mi], &bt[0]);
                    mma_f16(acc[mi][nj*2+1], ah[mi], &bt[2]);
                }
            }
        }
    }
#undef ISSUE
    asm volatile("cp.async.wait_group 0;":::"memory");
    __syncthreads();

    float* w2s   = (float*)(dyn + EP_W2_OFF);
    float* biass = (float*)(dyn + EP_B1_OFF);
    ((float4*)w2s)[tid] = ((const float4*)(W2 + ((size_t)e*H_ + n0)*KK))[tid];
    if(tid < 32) ((float4*)biass)[tid] = ((const float4*)(b1 + (size_t)e*H_ + n0))[tid];
    __syncthreads();

    float* ht = (float*)dyn;
    const int g = lane >> 2, tg2 = (lane & 3)*2;
#pragma unroll
    for(int mi=0; mi<2; mi++){
        int rr = warp_m*32 + mi*16 + g;
#pragma unroll
        for(int ni=0; ni<8; ni++){
            int c0 = warp_n*64 + ni*8 + tg2;
            float2 v0, v1;
            v0.x = fmaxf(acc[mi][ni][0] + biass[c0],   0.f);
            v0.y = fmaxf(acc[mi][ni][1] + biass[c0+1], 0.f);
            v1.x = fmaxf(acc[mi][ni][2] + biass[c0],   0.f);
            v1.y = fmaxf(acc[mi][ni][3] + biass[c0+1], 0.f);
            *(float2*)&ht[(size_t)rr*HTS + c0]     = v0;
            *(float2*)&ht[(size_t)(rr+8)*HTS + c0] = v1;
        }
    }
    __syncthreads();
    {
        const int row = tid >> 1, q = tid & 1;
        const float* hp = &ht[(size_t)row*HTS + q*64];
        const float* wp = &w2s[q*64*8];
        float pl[8];
#pragma unroll
        for(int k=0;k<8;k++) pl[k]=0.f;
#pragma unroll
        for(int cc=0; cc<64; cc++){
            int cr = (cc + q*9) & 63;
            float h = hp[cr];
            const float4* w4 = (const float4*)&wp[cr*8];
            float4 wa = w4[0], wb = w4[1];
            pl[0]=fmaf(h,wa.x,pl[0]); pl[1]=fmaf(h,wa.y,pl[1]);
            pl[2]=fmaf(h,wa.z,pl[2]); pl[3]=fmaf(h,wa.w,pl[3]);
            pl[4]=fmaf(h,wb.x,pl[4]); pl[5]=fmaf(h,wb.y,pl[5]);
            pl[6]=fmaf(h,wb.z,pl[6]); pl[7]=fmaf(h,wb.w,pl[7]);
        }
#pragma unroll
        for(int k=0;k<8;k++) pl[k] += __shfl_xor_sync(0xFFFFFFFFu, pl[k], 1);
        float* dst = gPart + (((size_t)(m0+row)*180) + (e*20 + blockIdx.y))*KK + q*4;
        *(float4*)dst = make_float4(pl[q*4], pl[q*4+1], pl[q*4+2], pl[q*4+3]);
    }
}

// ---- tail (unchanged)
__global__ __launch_bounds__(256) void tail_kernel(const float* __restrict__ b2,
                                                   float* __restrict__ out){
    const int b = blockIdx.x, tid = threadIdx.x;
    __shared__ float part[180][8];
    __shared__ float logits_s[9][8];
    __shared__ float probs_s[9][8];
    {
        const float4* src = (const float4*)(gPart + (size_t)b*180*KK);
        float4* dst4 = (float4*)&part[0][0];
        for(int i=tid; i<180*2; i+=256) dst4[i] = src[i];
    }
    __syncthreads();
    if(tid < 72){
        int e = tid>>3, k = tid&7;
        float s = 0.f;
#pragma unroll
        for(int j=0;j<20;j++) s += part[e*20+j][k];
        float lv = s + b2[tid];
        logits_s[e][k] = lv;
        out[(size_t)B_*73 + ((size_t)e*B_ + b)*KK + k] = lv;
    }
    __syncthreads();
    if(tid < 9){
        float m = -INFINITY;
#pragma unroll
        for(int k=0;k<8;k++) m = fmaxf(m, logits_s[tid][k]);
        float ex[8], s = 0.f;
#pragma unroll
        for(int k=0;k<8;k++){ ex[k] = expf(logits_s[tid][k]-m); s += ex[k]; }
        float inv = 1.f/s;
#pragma unroll
        for(int k=0;k<8;k++) probs_s[tid][k] = ex[k]*inv;
    }
    __syncthreads();
    if(tid < 73){
        float v;
        if(tid==0) v = 1.f;
        else if(tid<9) v = probs_s[0][tid-1];
        else { int t = tid-9; v = probs_s[0][t>>3]*probs_s[1+(t>>3)][t&7]; }
        out[(size_t)b*73 + tid] = v;
    }
}

extern "C" void kernel_launch(void* const* d_in, const int* in_sizes, int n_in,
                              void* d_out, int out_size){
    const float* x  = (const float*)d_in[0];
    const float* W1 = (const float*)d_in[1];
    const float* b1 = (const float*)d_in[2];
    const float* W2 = (const float*)d_in[3];
    const float* b2 = (const float*)d_in[4];
    float* out = (float*)d_out;

    cudaFuncSetAttribute(conv_all_kernel, cudaFuncAttributeMaxDynamicSharedMemorySize, CONV_DYN);
    cudaFuncSetAttribute(gemm_kernel, cudaFuncAttributeMaxDynamicSharedMemorySize, DYN_BYTES);

    conv_all_kernel<<<NXC + NWC, 256, CONV_DYN>>>(x, W1);
    dim3 grid(4, 20, 9);
    gemm_kernel<<<grid, 256, DYN_BYTES>>>(W2, b1);
    tail_kernel<<<B_, 256>>>(b2, out);
}